// round 1
// baseline (speedup 1.0000x reference)
#include <cuda_runtime.h>
#include <cuda_bf16.h>
#include <math.h>

// Problem constants
#define B 8
#define C 64
#define H 256
#define W 256
#define HW 65536
#define P 16
#define OC 64
#define NBINS 256
#define OUTC 112   // OC + (C-P)

// Device scratch (no allocation allowed)
__device__ float g_min[B * C];
__device__ float g_max[B * C];
__device__ float g_act[B * C];
__device__ int   g_top[B * P];
__device__ int   g_unsel[B * (C - P)];

// ---------------------------------------------------------------------------
// Kernel 1: per-(b,c) min/max over H*W
// ---------------------------------------------------------------------------
__global__ void k_minmax(const float* __restrict__ x) {
    __shared__ float smn[256], smx[256];
    int bc = blockIdx.x;
    const float4* p = (const float4*)(x + (size_t)bc * HW);
    float mn = 3.402823466e+38f, mx = -3.402823466e+38f;
    for (int i = threadIdx.x; i < HW / 4; i += 256) {
        float4 v = p[i];
        mn = fminf(mn, fminf(fminf(v.x, v.y), fminf(v.z, v.w)));
        mx = fmaxf(mx, fmaxf(fmaxf(v.x, v.y), fmaxf(v.z, v.w)));
    }
    smn[threadIdx.x] = mn; smx[threadIdx.x] = mx;
    __syncthreads();
    for (int s = 128; s > 0; s >>= 1) {
        if (threadIdx.x < s) {
            smn[threadIdx.x] = fminf(smn[threadIdx.x], smn[threadIdx.x + s]);
            smx[threadIdx.x] = fmaxf(smx[threadIdx.x], smx[threadIdx.x + s]);
        }
        __syncthreads();
    }
    if (threadIdx.x == 0) { g_min[bc] = smn[0]; g_max[bc] = smx[0]; }
}

// ---------------------------------------------------------------------------
// Kernel 2: per-(b,c) 256-bin histogram + entropy
// Bin path must match JAX bit-for-bit-ish: IEEE div, *256.0f, trunc-to-int.
// ---------------------------------------------------------------------------
__global__ void k_hist(const float* __restrict__ x) {
    __shared__ int   sh[NBINS];
    __shared__ float sred[256];
    int bc = blockIdx.x;
    int tid = threadIdx.x;
    sh[tid] = 0;
    __syncthreads();

    float mn = g_min[bc];
    float denom = g_max[bc] - mn + 1e-8f;
    const float4* p = (const float4*)(x + (size_t)bc * HW);
    for (int i = tid; i < HW / 4; i += 256) {
        float4 v = p[i];
        float vs[4] = {v.x, v.y, v.z, v.w};
#pragma unroll
        for (int k = 0; k < 4; k++) {
            float xn = __fdiv_rn(vs[k] - mn, denom);
            int bn = (int)(xn * 256.0f);          // trunc toward zero, like astype(int32)
            bn = bn < 0 ? 0 : (bn > 255 ? 255 : bn);
            atomicAdd(&sh[bn], 1);
        }
    }
    __syncthreads();

    float hv = (float)sh[tid] + 1e-8f;            // hist + eps in fp32
    sred[tid] = hv;
    __syncthreads();
    for (int s = 128; s > 0; s >>= 1) {
        if (tid < s) sred[tid] += sred[tid + s];
        __syncthreads();
    }
    float total = sred[0];
    __syncthreads();

    float prob = __fdiv_rn(hv, total);
    float term = prob * logf(prob + 1e-8f);
    sred[tid] = term;
    __syncthreads();
    for (int s = 128; s > 0; s >>= 1) {
        if (tid < s) sred[tid] += sred[tid + s];
        __syncthreads();
    }
    if (tid == 0) g_act[bc] = -sred[0];
}

// ---------------------------------------------------------------------------
// Kernel 3: top-16 selection per batch (stable: ties -> lower index first),
// and ascending-order list of unselected channels.
// ---------------------------------------------------------------------------
__global__ void k_topk() {
    int b = blockIdx.x;
    if (threadIdx.x != 0) return;
    float a[C];
    bool used[C];
    for (int c = 0; c < C; c++) { a[c] = g_act[b * C + c]; used[c] = false; }
    for (int p = 0; p < P; p++) {
        float best = -3.402823466e+38f;
        int bi = -1;
        for (int c = 0; c < C; c++) {
            if (!used[c] && a[c] > best) { best = a[c]; bi = c; }
        }
        used[bi] = true;
        g_top[b * P + p] = bi;
    }
    int k = 0;
    for (int c = 0; c < C; c++)
        if (!used[c]) g_unsel[b * (C - P) + (k++)] = c;
}

// ---------------------------------------------------------------------------
// Kernel 4: direct 3x3 conv on 16 selected channels -> 64 output channels.
// Tile: 16(h) x 64(w) per block, all 64 OC per block.
// 256 threads = 64 w-lanes x 4 oc-groups; each thread: 4 rows x 16 OCs regs.
// Input tile (with halo) + full weights staged in dynamic smem.
// ---------------------------------------------------------------------------
#define TH 16
#define TW 64
#define IROWS (TH + 2)     // 18
#define ICOLS (TW + 2)     // 66
#define SIN_SZ (P * IROWS * ICOLS)   // 19008 floats
#define SW_SZ  (OC * P * 9)          // 9216 floats
#define CONV_SMEM ((SIN_SZ + SW_SZ) * 4)

__global__ void __launch_bounds__(256, 1)
k_conv(const float* __restrict__ x, const float* __restrict__ wgt,
       const float* __restrict__ bias, float* __restrict__ out) {
    extern __shared__ float smem[];
    float* sIn = smem;            // [P][IROWS][ICOLS]
    float* sW  = smem + SIN_SZ;   // [OC][P][3][3]
    __shared__ float sB[OC];

    int b   = blockIdx.z;
    int th0 = blockIdx.y * TH;
    int tw0 = blockIdx.x * TW;
    int tid = threadIdx.x;

    for (int i = tid; i < SW_SZ; i += 256) sW[i] = wgt[i];
    if (tid < OC) sB[tid] = bias[tid];

    // stage input tile with halo (zero-pad outside image)
    for (int i = tid; i < SIN_SZ; i += 256) {
        int ic  = i / (IROWS * ICOLS);
        int rem = i - ic * (IROWS * ICOLS);
        int r = rem / ICOLS;
        int c = rem - r * ICOLS;
        int gh = th0 + r - 1;
        int gw = tw0 + c - 1;
        float v = 0.f;
        if (gh >= 0 && gh < H && gw >= 0 && gw < W) {
            int ch = g_top[b * P + ic];
            v = x[((size_t)(b * C + ch)) * HW + gh * W + gw];
        }
        sIn[i] = v;
    }
    __syncthreads();

    int wt = tid & 63;        // w lane within tile
    int g  = tid >> 6;        // oc group: handles oc = g*16 .. g*16+15

    for (int hc = 0; hc < 4; hc++) {      // 4 chunks of 4 rows
        float acc[4][16];
#pragma unroll
        for (int r = 0; r < 4; r++)
#pragma unroll
            for (int j = 0; j < 16; j++) acc[r][j] = 0.f;

#pragma unroll 4
        for (int ic = 0; ic < P; ic++) {
            const float* wbase = sW + (g * 16 * P + ic) * 9;   // + j*(P*9) per oc
            const float* ibase = sIn + ic * (IROWS * ICOLS) + (hc * 4) * ICOLS + wt;
#pragma unroll
            for (int kh = 0; kh < 3; kh++) {
                const float* irow = ibase + kh * ICOLS;
#pragma unroll
                for (int kw = 0; kw < 3; kw++) {
                    float wv[16];
#pragma unroll
                    for (int j = 0; j < 16; j++) wv[j] = wbase[j * (P * 9) + kh * 3 + kw];
                    float iv[4];
#pragma unroll
                    for (int r = 0; r < 4; r++) iv[r] = irow[r * ICOLS + kw];
#pragma unroll
                    for (int r = 0; r < 4; r++)
#pragma unroll
                        for (int j = 0; j < 16; j++)
                            acc[r][j] = fmaf(iv[r], wv[j], acc[r][j]);
                }
            }
        }

#pragma unroll
        for (int j = 0; j < 16; j++) {
            int oc = g * 16 + j;
            float bb = sB[oc];
            size_t base = ((size_t)b * OUTC + oc) * HW + (size_t)(th0 + hc * 4) * W + tw0 + wt;
#pragma unroll
            for (int r = 0; r < 4; r++)
                out[base + (size_t)r * W] = acc[r][j] + bb;
        }
    }
}

// ---------------------------------------------------------------------------
// Kernel 5: copy unselected channels (ascending order) into out[:, 64:112]
// ---------------------------------------------------------------------------
__global__ void k_copy(const float* __restrict__ x, float* __restrict__ out) {
    size_t t = (size_t)blockIdx.x * 256 + threadIdx.x;   // one float4 each
    const size_t total = (size_t)B * (C - P) * (HW / 4);
    if (t >= total) return;
    int ch_slot = (int)(t >> 14);         // / (HW/4 = 16384)
    int off     = (int)(t & 16383);
    int b = ch_slot / (C - P);
    int j = ch_slot - b * (C - P);
    int c = g_unsel[b * (C - P) + j];
    const float4* src = (const float4*)(x + ((size_t)(b * C + c)) * HW);
    float4* dst = (float4*)(out + (((size_t)b * OUTC) + OC + j) * HW);
    dst[off] = src[off];
}

// ---------------------------------------------------------------------------
extern "C" void kernel_launch(void* const* d_in, const int* in_sizes, int n_in,
                              void* d_out, int out_size) {
    const float* x    = (const float*)d_in[0];
    const float* wgt  = (const float*)d_in[1];
    const float* bias = (const float*)d_in[2];
    float* out = (float*)d_out;

    cudaFuncSetAttribute(k_conv, cudaFuncAttributeMaxDynamicSharedMemorySize, CONV_SMEM);

    k_minmax<<<B * C, 256>>>(x);
    k_hist<<<B * C, 256>>>(x);
    k_topk<<<B, 32>>>();
    k_conv<<<dim3(W / TW, H / TH, B), 256, CONV_SMEM>>>(x, wgt, bias, out);

    int copy_blocks = (B * (C - P) * (HW / 4) + 255) / 256;
    k_copy<<<copy_blocks, 256>>>(x, out);
}

// round 2
// speedup vs baseline: 1.1915x; 1.1915x over previous
#include <cuda_runtime.h>
#include <cuda_bf16.h>
#include <math.h>

#define B 8
#define C 64
#define H 256
#define W 256
#define HW 65536
#define P 16
#define OC 64
#define NBINS 256
#define OUTC 112   // OC + (C-P)

// Device scratch
__device__ float g_act[B * C];
__device__ int   g_top[B * P];
__device__ int   g_unsel[B * (C - P)];

// packed f32x2 helpers
__device__ __forceinline__ unsigned long long pack2(float lo, float hi) {
    unsigned long long r;
    asm("mov.b64 %0, {%1, %2};" : "=l"(r) : "f"(lo), "f"(hi));
    return r;
}
__device__ __forceinline__ void unpack2(unsigned long long v, float& lo, float& hi) {
    asm("mov.b64 {%0, %1}, %2;" : "=f"(lo), "=f"(hi) : "l"(v));
}
__device__ __forceinline__ unsigned long long fma2(unsigned long long a,
                                                   unsigned long long b,
                                                   unsigned long long c) {
    unsigned long long d;
    asm("fma.rn.f32x2 %0, %1, %2, %3;" : "=l"(d) : "l"(a), "l"(b), "l"(c));
    return d;
}

// ---------------------------------------------------------------------------
// Kernel 1: fused per-(b,c) min/max + 256-bin histogram + entropy.
// Pass 2 re-reads the channel (hits L2). Per-warp sub-histograms cut
// same-address ATOMS serialization.
// ---------------------------------------------------------------------------
__global__ void k_stats(const float* __restrict__ x) {
    __shared__ float smn[256], smx[256];
    __shared__ int   sh[8][NBINS];
    __shared__ float sred[256];
    __shared__ float s_mn, s_den;

    int bc  = blockIdx.x;
    int tid = threadIdx.x;
    int wid = tid >> 5;
    const float4* p = (const float4*)(x + (size_t)bc * HW);

    // pass 1: min/max
    float mn = 3.402823466e+38f, mx = -3.402823466e+38f;
    for (int i = tid; i < HW / 4; i += 256) {
        float4 v = p[i];
        mn = fminf(mn, fminf(fminf(v.x, v.y), fminf(v.z, v.w)));
        mx = fmaxf(mx, fmaxf(fmaxf(v.x, v.y), fmaxf(v.z, v.w)));
    }
    smn[tid] = mn; smx[tid] = mx;
    // zero sub-histograms while waiting
    for (int w = 0; w < 8; w++) sh[w][tid] = 0;
    __syncthreads();
    for (int s = 128; s > 0; s >>= 1) {
        if (tid < s) {
            smn[tid] = fminf(smn[tid], smn[tid + s]);
            smx[tid] = fmaxf(smx[tid], smx[tid + s]);
        }
        __syncthreads();
    }
    if (tid == 0) { s_mn = smn[0]; s_den = smx[0] - smn[0] + 1e-8f; }
    __syncthreads();

    // pass 2: histogram (bin path matches JAX: IEEE div, *256, trunc cast)
    float bmn = s_mn, bden = s_den;
    int* myh = sh[wid];
    for (int i = tid; i < HW / 4; i += 256) {
        float4 v = p[i];
        float vs[4] = {v.x, v.y, v.z, v.w};
#pragma unroll
        for (int k = 0; k < 4; k++) {
            float xn = __fdiv_rn(vs[k] - bmn, bden);
            int bn = (int)(xn * 256.0f);
            bn = bn < 0 ? 0 : (bn > 255 ? 255 : bn);
            atomicAdd(&myh[bn], 1);
        }
    }
    __syncthreads();

    int cnt = 0;
#pragma unroll
    for (int w = 0; w < 8; w++) cnt += sh[w][tid];
    float hv = (float)cnt + 1e-8f;
    sred[tid] = hv;
    __syncthreads();
    for (int s = 128; s > 0; s >>= 1) {
        if (tid < s) sred[tid] += sred[tid + s];
        __syncthreads();
    }
    float total = sred[0];
    __syncthreads();

    float prob = __fdiv_rn(hv, total);
    sred[tid] = prob * logf(prob + 1e-8f);
    __syncthreads();
    for (int s = 128; s > 0; s >>= 1) {
        if (tid < s) sred[tid] += sred[tid + s];
        __syncthreads();
    }
    if (tid == 0) g_act[bc] = -sred[0];
}

// ---------------------------------------------------------------------------
// Kernel 2: top-16 per batch (stable tie-break) + ascending unselected list.
// ---------------------------------------------------------------------------
__global__ void k_topk() {
    int b = blockIdx.x;
    if (threadIdx.x != 0) return;
    float a[C];
    bool used[C];
    for (int c = 0; c < C; c++) { a[c] = g_act[b * C + c]; used[c] = false; }
    for (int p = 0; p < P; p++) {
        float best = -3.402823466e+38f;
        int bi = -1;
        for (int c = 0; c < C; c++)
            if (!used[c] && a[c] > best) { best = a[c]; bi = c; }
        used[bi] = true;
        g_top[b * P + p] = bi;
    }
    int k = 0;
    for (int c = 0; c < C; c++)
        if (!used[c]) g_unsel[b * (C - P) + (k++)] = c;
}

// ---------------------------------------------------------------------------
// Kernel 3: direct 3x3 conv, 16 selected ch -> 64 OC, packed f32x2 math.
// Tile 16(h) x 64(w); 256 threads = 64 w-lanes x 4 groups of 16 OCs.
// Weights staged in smem transposed to [P*9][OC] so an OC-pair is one LDS.64
// directly usable as a packed f32x2 operand.
// ---------------------------------------------------------------------------
#define TH 16
#define TW 64
#define IROWS (TH + 2)
#define ICOLS (TW + 2)
#define SIN_SZ (P * IROWS * ICOLS)   // 19008 floats
#define SW_SZ  (P * 9 * OC)          // 9216 floats, layout [tap][oc]
#define CONV_SMEM ((SIN_SZ + SW_SZ) * 4)

__global__ void __launch_bounds__(256, 1)
k_conv(const float* __restrict__ x, const float* __restrict__ wgt,
       const float* __restrict__ bias, float* __restrict__ out) {
    extern __shared__ float smem[];
    float* sIn = smem;            // [P][IROWS][ICOLS]
    float* sW  = smem + SIN_SZ;   // [P*9][OC]  (tap-major, oc contiguous)
    __shared__ float sB[OC];

    int b   = blockIdx.z;
    int th0 = blockIdx.y * TH;
    int tw0 = blockIdx.x * TW;
    int tid = threadIdx.x;

    // stage weights transposed: wgt[oc][ic][kh][kw] -> sW[(ic*9+kh*3+kw)*OC + oc]
    for (int i = tid; i < SW_SZ; i += 256) {
        int oc  = i / (P * 9);
        int tap = i - oc * (P * 9);
        sW[tap * OC + oc] = wgt[i];
    }
    if (tid < OC) sB[tid] = bias[tid];

    // stage input tile with halo
    for (int i = tid; i < SIN_SZ; i += 256) {
        int ic  = i / (IROWS * ICOLS);
        int rem = i - ic * (IROWS * ICOLS);
        int r = rem / ICOLS;
        int c = rem - r * ICOLS;
        int gh = th0 + r - 1;
        int gw = tw0 + c - 1;
        float v = 0.f;
        if (gh >= 0 && gh < H && gw >= 0 && gw < W) {
            int ch = g_top[b * P + ic];
            v = x[((size_t)(b * C + ch)) * HW + gh * W + gw];
        }
        sIn[i] = v;
    }
    __syncthreads();

    int wt = tid & 63;        // w lane
    int g  = tid >> 6;        // oc group: oc = g*16 + [0,16)

    for (int hc = 0; hc < 4; hc++) {          // 4 chunks of 4 rows
        unsigned long long acc[4][8];         // [row][ocpair], packed f32x2
#pragma unroll
        for (int r = 0; r < 4; r++)
#pragma unroll
            for (int j = 0; j < 8; j++) acc[r][j] = 0ull;

        for (int ic = 0; ic < P; ic++) {
            const float* ibase = sIn + ic * (IROWS * ICOLS) + (hc * 4) * ICOLS + wt;
#pragma unroll
            for (int kh = 0; kh < 3; kh++) {
                const float* irow = ibase + kh * ICOLS;
#pragma unroll
                for (int kw = 0; kw < 3; kw++) {
                    unsigned long long ivp[4];
#pragma unroll
                    for (int r = 0; r < 4; r++) {
                        float v = irow[r * ICOLS + kw];
                        ivp[r] = pack2(v, v);
                    }
                    const unsigned long long* w2 = (const unsigned long long*)
                        (sW + (ic * 9 + kh * 3 + kw) * OC + g * 16);
#pragma unroll
                    for (int j = 0; j < 8; j++) {
                        unsigned long long wp = w2[j];   // LDS.64, broadcast in warp
#pragma unroll
                        for (int r = 0; r < 4; r++)
                            acc[r][j] = fma2(ivp[r], wp, acc[r][j]);
                    }
                }
            }
        }

#pragma unroll
        for (int j = 0; j < 8; j++) {
            int oc0 = g * 16 + 2 * j;
            float b0 = sB[oc0], b1 = sB[oc0 + 1];
            size_t base0 = ((size_t)b * OUTC + oc0) * HW
                         + (size_t)(th0 + hc * 4) * W + tw0 + wt;
#pragma unroll
            for (int r = 0; r < 4; r++) {
                float lo, hi;
                unpack2(acc[r][j], lo, hi);
                out[base0 + (size_t)r * W]      = lo + b0;
                out[base0 + HW + (size_t)r * W] = hi + b1;
            }
        }
    }
}

// ---------------------------------------------------------------------------
// Kernel 4: copy unselected channels (ascending) into out[:, 64:112]
// ---------------------------------------------------------------------------
__global__ void k_copy(const float* __restrict__ x, float* __restrict__ out) {
    size_t t = (size_t)blockIdx.x * 256 + threadIdx.x;
    const size_t total = (size_t)B * (C - P) * (HW / 4);
    if (t >= total) return;
    int ch_slot = (int)(t >> 14);
    int off     = (int)(t & 16383);
    int b = ch_slot / (C - P);
    int j = ch_slot - b * (C - P);
    int c = g_unsel[b * (C - P) + j];
    const float4* src = (const float4*)(x + ((size_t)(b * C + c)) * HW);
    float4* dst = (float4*)(out + (((size_t)b * OUTC) + OC + j) * HW);
    dst[off] = src[off];
}

// ---------------------------------------------------------------------------
extern "C" void kernel_launch(void* const* d_in, const int* in_sizes, int n_in,
                              void* d_out, int out_size) {
    const float* x    = (const float*)d_in[0];
    const float* wgt  = (const float*)d_in[1];
    const float* bias = (const float*)d_in[2];
    float* out = (float*)d_out;

    cudaFuncSetAttribute(k_conv, cudaFuncAttributeMaxDynamicSharedMemorySize, CONV_SMEM);

    k_stats<<<B * C, 256>>>(x);
    k_topk<<<B, 32>>>();
    k_conv<<<dim3(W / TW, H / TH, B), 256, CONV_SMEM>>>(x, wgt, bias, out);

    int copy_blocks = (B * (C - P) * (HW / 4) + 255) / 256;
    k_copy<<<copy_blocks, 256>>>(x, out);
}

// round 4
// speedup vs baseline: 1.4330x; 1.2027x over previous
#include <cuda_runtime.h>
#include <cuda_bf16.h>
#include <math.h>
#include <cstdint>

#define B 8
#define C 64
#define H 256
#define W 256
#define HW 65536
#define P 16
#define OC 64
#define NBINS 256
#define OUTC 112   // OC + (C-P)

// Device scratch
__device__ float g_act[B * C];
__device__ int   g_top[B * P];
__device__ int   g_unsel[B * (C - P)];

__device__ __forceinline__ uint32_t f2tf32(float v) {
    uint32_t u;
    asm("cvt.rna.tf32.f32 %0, %1;" : "=r"(u) : "f"(v));
    return u;
}

// ===========================================================================
// Kernel 1: fused per-(b,c) min/max + 256-bin histogram + entropy.
// ===========================================================================
__global__ void k_stats(const float* __restrict__ x) {
    __shared__ float smn[256], smx[256];
    __shared__ int   sh[8][NBINS];
    __shared__ float sred[256];
    __shared__ float s_mn, s_den;

    int bc  = blockIdx.x;
    int tid = threadIdx.x;
    int wid = tid >> 5;
    const float4* p = (const float4*)(x + (size_t)bc * HW);

    float mn = 3.402823466e+38f, mx = -3.402823466e+38f;
    for (int i = tid; i < HW / 4; i += 256) {
        float4 v = p[i];
        mn = fminf(mn, fminf(fminf(v.x, v.y), fminf(v.z, v.w)));
        mx = fmaxf(mx, fmaxf(fmaxf(v.x, v.y), fmaxf(v.z, v.w)));
    }
    smn[tid] = mn; smx[tid] = mx;
    for (int w = 0; w < 8; w++) sh[w][tid] = 0;
    __syncthreads();
    for (int s = 128; s > 0; s >>= 1) {
        if (tid < s) {
            smn[tid] = fminf(smn[tid], smn[tid + s]);
            smx[tid] = fmaxf(smx[tid], smx[tid + s]);
        }
        __syncthreads();
    }
    if (tid == 0) { s_mn = smn[0]; s_den = smx[0] - smn[0] + 1e-8f; }
    __syncthreads();

    float bmn = s_mn, bden = s_den;
    int* myh = sh[wid];
    for (int i = tid; i < HW / 4; i += 256) {
        float4 v = p[i];
        float vs[4] = {v.x, v.y, v.z, v.w};
#pragma unroll
        for (int k = 0; k < 4; k++) {
            float xn = __fdiv_rn(vs[k] - bmn, bden);
            int bn = (int)(xn * 256.0f);
            bn = bn < 0 ? 0 : (bn > 255 ? 255 : bn);
            atomicAdd(&myh[bn], 1);
        }
    }
    __syncthreads();

    int cnt = 0;
#pragma unroll
    for (int w = 0; w < 8; w++) cnt += sh[w][tid];
    float hv = (float)cnt + 1e-8f;
    sred[tid] = hv;
    __syncthreads();
    for (int s = 128; s > 0; s >>= 1) {
        if (tid < s) sred[tid] += sred[tid + s];
        __syncthreads();
    }
    float total = sred[0];
    __syncthreads();

    float prob = __fdiv_rn(hv, total);
    sred[tid] = prob * logf(prob + 1e-8f);
    __syncthreads();
    for (int s = 128; s > 0; s >>= 1) {
        if (tid < s) sred[tid] += sred[tid + s];
        __syncthreads();
    }
    if (tid == 0) g_act[bc] = -sred[0];
}

// ===========================================================================
// Kernel 2: top-16 per batch (stable tie-break) + ascending unselected list.
// ===========================================================================
__global__ void k_topk() {
    int b = blockIdx.x;
    if (threadIdx.x != 0) return;
    float a[C];
    bool used[C];
    for (int c = 0; c < C; c++) { a[c] = g_act[b * C + c]; used[c] = false; }
    for (int p = 0; p < P; p++) {
        float best = -3.402823466e+38f;
        int bi = -1;
        for (int c = 0; c < C; c++)
            if (!used[c] && a[c] > best) { best = a[c]; bi = c; }
        used[bi] = true;
        g_top[b * P + p] = bi;
    }
    int k = 0;
    for (int c = 0; c < C; c++)
        if (!used[c]) g_unsel[b * (C - P) + (k++)] = c;
}

// ===========================================================================
// Kernel 3: warp-level tf32 mma.sync implicit-GEMM conv.
// Tile = 128 consecutive pixels of one image row x 64 OC, one tile per block.
// A (smem): patch pixel-major [3*132 slots][16 ch], pitch 20 (conflict-free).
// B (smem): weights [9 tap * 16 ic][64 oc], pitch 72 (conflict-free).
// 8 warps x 16 pixels; K = 144 (= 9 taps * 16 ch) in 18 k-steps of 8.
// Epilogue bounces through smem for coalesced stores.
// ===========================================================================
#define APITCH 20
#define BPITCH 72
#define SIN_FLOATS (3 * 132 * APITCH)        // 23760
#define SW_FLOATS  (144 * BPITCH)            // 10368
#define CONV_SMEM  ((SIN_FLOATS + SW_FLOATS) * 4)   // 136512 bytes? no:
// 23760*4 + 10368*4 = 95040 + 41472 = 136512 -> too big? 228KB limit, ok but
// occupancy 1. Keep; blocks are short-lived and grid is huge.
#define NTILES (B * H * (W / 128))           // 4096

__global__ void __launch_bounds__(256, 1)
k_conv_mma(const float* __restrict__ x, const float* __restrict__ wgt,
           const float* __restrict__ bias, float* __restrict__ out) {
    extern __shared__ char smem_raw[];
    uint32_t* sIn = (uint32_t*)smem_raw;                 // tf32 bits
    uint32_t* sW  = ((uint32_t*)smem_raw) + SIN_FLOATS;  // tf32 bits
    float*    sOut = (float*)smem_raw;                   // overlay after MMA
    __shared__ float sB[OC];
    __shared__ int   sTop[P];

    int tid  = threadIdx.x;
    int wid  = tid >> 5;
    int lane = tid & 31;

    int t   = blockIdx.x;
    int b   = t >> 9;
    int rem = t & 511;
    int h   = rem >> 1;
    int w0  = (rem & 1) << 7;

    if (tid < P)  sTop[tid] = g_top[b * P + tid];
    if (tid < OC) sB[tid]  = bias[tid];

    // ---- stage weights: wgt[oc][ic][kh][kw] -> sW[(tap*16+ic)*BPITCH + oc]
    for (int i = tid; i < OC * P * 9; i += 256) {
        int oc  = i / (P * 9);
        int rem2 = i - oc * (P * 9);
        int ic  = rem2 / 9;
        int tap = rem2 - ic * 9;
        sW[(tap * 16 + ic) * BPITCH + oc] = f2tf32(wgt[i]);
    }
    __syncthreads();   // sTop ready before staging uses it

    // ---- stage patch: 130 pixel slots x 3 rows x 16 ch (tf32 bits)
    if (tid < 130) {
        int pp = tid;
        int gw = w0 - 1 + pp;
        bool wok = ((unsigned)gw < (unsigned)W);
        const float* srcb = x + ((size_t)b * C) * HW + gw;
#pragma unroll
        for (int pr = 0; pr < 3; pr++) {
            int gh = h - 1 + pr;
            uint32_t q[16];
            if (wok && (unsigned)gh < (unsigned)H) {
                const float* src = srcb + gh * W;
#pragma unroll
                for (int c = 0; c < 16; c++)
                    q[c] = f2tf32(src[(size_t)sTop[c] * HW]);
            } else {
#pragma unroll
                for (int c = 0; c < 16; c++) q[c] = 0u;
            }
            uint32_t* dst = sIn + (pr * 132 + pp) * APITCH;
#pragma unroll
            for (int c = 0; c < 16; c++) dst[c] = q[c];
        }
    }
    __syncthreads();

    // ---- MMA mainloop ----
    float acc[8][4];
#pragma unroll
    for (int j = 0; j < 8; j++)
#pragma unroll
        for (int r = 0; r < 4; r++) acc[j][r] = 0.f;

    int gp = lane >> 2;          // group id 0..7
    int kc = lane & 3;           // col-in-group
    int p0 = wid * 16 + gp;      // A row (pixel) for a0/a2

#pragma unroll
    for (int tap = 0; tap < 9; tap++) {
        int kh = tap / 3, kw = tap - kh * 3;
        int arow0 = kh * 132 + kw;
#pragma unroll
        for (int ks = 0; ks < 2; ks++) {
            uint32_t a0 = sIn[(arow0 + p0)     * APITCH + ks * 8 + kc];
            uint32_t a1 = sIn[(arow0 + p0 + 8) * APITCH + ks * 8 + kc];
            uint32_t a2 = sIn[(arow0 + p0)     * APITCH + ks * 8 + kc + 4];
            uint32_t a3 = sIn[(arow0 + p0 + 8) * APITCH + ks * 8 + kc + 4];
            int kr = tap * 16 + ks * 8 + kc;
            const uint32_t* brow0 = sW + kr * BPITCH + gp;
            const uint32_t* brow1 = brow0 + 4 * BPITCH;
#pragma unroll
            for (int j = 0; j < 8; j++) {
                uint32_t b0 = brow0[j * 8];
                uint32_t b1 = brow1[j * 8];
                asm volatile(
                    "mma.sync.aligned.m16n8k8.row.col.f32.tf32.tf32.f32 "
                    "{%0,%1,%2,%3}, {%4,%5,%6,%7}, {%8,%9}, {%0,%1,%2,%3};"
                    : "+f"(acc[j][0]), "+f"(acc[j][1]),
                      "+f"(acc[j][2]), "+f"(acc[j][3])
                    : "r"(a0), "r"(a1), "r"(a2), "r"(a3), "r"(b0), "r"(b1));
            }
        }
    }
    __syncthreads();   // done reading sIn/sW; smem becomes sOut

    // ---- write accumulators to sOut[oc][132 pitch] (conflict-free) ----
#pragma unroll
    for (int j = 0; j < 8; j++) {
        int oc0 = j * 8 + 2 * kc;
        int px  = wid * 16 + gp;
        sOut[oc0 * 132 + px]           = acc[j][0];
        sOut[(oc0 + 1) * 132 + px]     = acc[j][1];
        sOut[oc0 * 132 + px + 8]       = acc[j][2];
        sOut[(oc0 + 1) * 132 + px + 8] = acc[j][3];
    }
    __syncthreads();

    // ---- coalesced store: 64 oc rows x 128 px, + bias ----
    int r  = tid >> 2;              // oc row
    int c0 = (tid & 3) * 32;        // col segment
    float bb = sB[r];
    float* ob = out + ((size_t)b * OUTC + r) * HW + h * W + w0 + c0;
    const float* sr = sOut + r * 132 + c0;
#pragma unroll
    for (int q = 0; q < 8; q++) {
        float4 v = *(const float4*)(sr + q * 4);
        v.x += bb; v.y += bb; v.z += bb; v.w += bb;
        *(float4*)(ob + q * 4) = v;
    }
}

// ===========================================================================
// Kernel 4: copy unselected channels (ascending) into out[:, 64:112]
// ===========================================================================
__global__ void k_copy(const float* __restrict__ x, float* __restrict__ out) {
    size_t t = (size_t)blockIdx.x * 256 + threadIdx.x;
    const size_t total = (size_t)B * (C - P) * (HW / 4);
    if (t >= total) return;
    int ch_slot = (int)(t >> 14);
    int off     = (int)(t & 16383);
    int b = ch_slot / (C - P);
    int j = ch_slot - b * (C - P);
    int c = g_unsel[b * (C - P) + j];
    const float4* src = (const float4*)(x + ((size_t)(b * C + c)) * HW);
    float4* dst = (float4*)(out + (((size_t)b * OUTC) + OC + j) * HW);
    dst[off] = src[off];
}

// ===========================================================================
extern "C" void kernel_launch(void* const* d_in, const int* in_sizes, int n_in,
                              void* d_out, int out_size) {
    const float* x    = (const float*)d_in[0];
    const float* wgt  = (const float*)d_in[1];
    const float* bias = (const float*)d_in[2];
    float* out = (float*)d_out;

    cudaFuncSetAttribute(k_conv_mma, cudaFuncAttributeMaxDynamicSharedMemorySize,
                         CONV_SMEM);

    k_stats<<<B * C, 256>>>(x);
    k_topk<<<B, 32>>>();
    k_conv_mma<<<NTILES, 256, CONV_SMEM>>>(x, wgt, bias, out);

    int copy_blocks = (B * (C - P) * (HW / 4) + 255) / 256;
    k_copy<<<copy_blocks, 256>>>(x, out);
}

// round 5
// speedup vs baseline: 1.5443x; 1.0776x over previous
#include <cuda_runtime.h>
#include <cuda_bf16.h>
#include <math.h>
#include <cstdint>

#define B 8
#define C 64
#define H 256
#define W 256
#define HW 65536
#define P 16
#define OC 64
#define NBINS 256
#define OUTC 112   // OC + (C-P)

// Device scratch
__device__ float g_act[B * C];
__device__ int   g_top[B * P];
__device__ int   g_unsel[B * (C - P)];

__device__ __forceinline__ uint32_t f2tf32(float v) {
    uint32_t u;
    asm("cvt.rna.tf32.f32 %0, %1;" : "=r"(u) : "f"(v));
    return u;
}

// ===========================================================================
// Kernel 1: fused per-(b,c) min/max + 256-bin histogram + entropy.
// ===========================================================================
__global__ void k_stats(const float* __restrict__ x) {
    __shared__ float smn[256], smx[256];
    __shared__ int   sh[8][NBINS];
    __shared__ float sred[256];
    __shared__ float s_mn, s_den;

    int bc  = blockIdx.x;
    int tid = threadIdx.x;
    int wid = tid >> 5;
    const float4* p = (const float4*)(x + (size_t)bc * HW);

    float mn = 3.402823466e+38f, mx = -3.402823466e+38f;
    for (int i = tid; i < HW / 4; i += 256) {
        float4 v = p[i];
        mn = fminf(mn, fminf(fminf(v.x, v.y), fminf(v.z, v.w)));
        mx = fmaxf(mx, fmaxf(fmaxf(v.x, v.y), fmaxf(v.z, v.w)));
    }
    smn[tid] = mn; smx[tid] = mx;
    for (int w = 0; w < 8; w++) sh[w][tid] = 0;
    __syncthreads();
    for (int s = 128; s > 0; s >>= 1) {
        if (tid < s) {
            smn[tid] = fminf(smn[tid], smn[tid + s]);
            smx[tid] = fmaxf(smx[tid], smx[tid + s]);
        }
        __syncthreads();
    }
    if (tid == 0) { s_mn = smn[0]; s_den = smx[0] - smn[0] + 1e-8f; }
    __syncthreads();

    float bmn = s_mn, bden = s_den;
    int* myh = sh[wid];
    for (int i = tid; i < HW / 4; i += 256) {
        float4 v = p[i];
        float vs[4] = {v.x, v.y, v.z, v.w};
#pragma unroll
        for (int k = 0; k < 4; k++) {
            float xn = __fdiv_rn(vs[k] - bmn, bden);
            int bn = (int)(xn * 256.0f);
            bn = bn < 0 ? 0 : (bn > 255 ? 255 : bn);
            atomicAdd(&myh[bn], 1);
        }
    }
    __syncthreads();

    int cnt = 0;
#pragma unroll
    for (int w = 0; w < 8; w++) cnt += sh[w][tid];
    float hv = (float)cnt + 1e-8f;
    sred[tid] = hv;
    __syncthreads();
    for (int s = 128; s > 0; s >>= 1) {
        if (tid < s) sred[tid] += sred[tid + s];
        __syncthreads();
    }
    float total = sred[0];
    __syncthreads();

    float prob = __fdiv_rn(hv, total);
    sred[tid] = prob * logf(prob + 1e-8f);
    __syncthreads();
    for (int s = 128; s > 0; s >>= 1) {
        if (tid < s) sred[tid] += sred[tid + s];
        __syncthreads();
    }
    if (tid == 0) g_act[bc] = -sred[0];
}

// ===========================================================================
// Kernel 2: top-16 per batch (stable tie-break) + ascending unselected list.
// ===========================================================================
__global__ void k_topk() {
    int b = blockIdx.x;
    if (threadIdx.x != 0) return;
    float a[C];
    bool used[C];
    for (int c = 0; c < C; c++) { a[c] = g_act[b * C + c]; used[c] = false; }
    for (int p = 0; p < P; p++) {
        float best = -3.402823466e+38f;
        int bi = -1;
        for (int c = 0; c < C; c++)
            if (!used[c] && a[c] > best) { best = a[c]; bi = c; }
        used[bi] = true;
        g_top[b * P + p] = bi;
    }
    int k = 0;
    for (int c = 0; c < C; c++)
        if (!used[c]) g_unsel[b * (C - P) + (k++)] = c;
}

// ===========================================================================
// Kernel 3 (fused): tf32 mma.sync conv on full-row tiles + untouched-copy.
// bid%3: 0,1 -> conv tile (2048 tiles, one image row each); 2 -> copy chunk
// (1024 chunks). Interleaving co-schedules the DRAM-bound copy with the
// compute-bound conv inside one kernel.
//
// Conv tile = 256 px x 64 oc. 8 warps x 32 px (two m16 chunks), K = 144
// (9 taps x 16 ch) in 18 k-steps of 8; 16 mma.m16n8k8 per warp per k-step.
// A smem [3][260 slots][16ch] pitch 20 (conflict-free);
// B smem [144][64 oc] pitch 72 (conflict-free).
// ===========================================================================
#define APITCH 20
#define AROW   260
#define BPITCH 72
#define SIN_FLOATS (3 * AROW * APITCH)       // 15600
#define SW_FLOATS  (144 * BPITCH)            // 10368
#define CONV_SMEM  ((SIN_FLOATS + SW_FLOATS) * 4)   // 103872 bytes
#define OPITCH 260
#define NCONV  (B * H)                       // 2048
#define NCOPY  1024
#define FUSED_GRID (NCONV + NCOPY)           // 3072
#define COPY_F4_TOTAL ((size_t)B * (C - P) * (HW / 4))   // 6291456
#define COPY_PER_CHUNK ((int)(COPY_F4_TOTAL / NCOPY))    // 6144

__global__ void __launch_bounds__(256, 2)
k_conv_mma(const float* __restrict__ x, const float* __restrict__ wgt,
           const float* __restrict__ bias, float* __restrict__ out) {
    extern __shared__ char smem_raw[];
    int tid  = threadIdx.x;
    int bid  = blockIdx.x;
    int grp  = bid / 3;
    int role = bid - grp * 3;

    // ---------------- copy role ----------------
    if (role == 2) {
        size_t base = (size_t)grp * COPY_PER_CHUNK;
        for (int i = tid; i < COPY_PER_CHUNK; i += 256) {
            size_t t = base + i;
            int ch_slot = (int)(t >> 14);
            int off     = (int)(t & 16383);
            int b = ch_slot / (C - P);
            int j = ch_slot - b * (C - P);
            int c = g_unsel[b * (C - P) + j];
            const float4* src = (const float4*)(x + ((size_t)(b * C + c)) * HW);
            float4* dst = (float4*)(out + (((size_t)b * OUTC) + OC + j) * HW);
            dst[off] = src[off];
        }
        return;
    }

    // ---------------- conv role ----------------
    uint32_t* sIn = (uint32_t*)smem_raw;                 // tf32 bits
    uint32_t* sW  = ((uint32_t*)smem_raw) + SIN_FLOATS;  // tf32 bits
    float*    sOut = (float*)smem_raw;                   // overlay after MMA
    __shared__ float sB[OC];
    __shared__ int   sTop[P];

    int wid  = tid >> 5;
    int lane = tid & 31;

    int tile = grp * 2 + role;        // 0..2047
    int b = tile >> 8;
    int h = tile & 255;

    if (tid < P)  sTop[tid] = g_top[b * P + tid];
    if (tid < OC) sB[tid]  = bias[tid];

    // stage weights: wgt[oc][ic][kh][kw] -> sW[(tap*16+ic)*BPITCH + oc]
    for (int i = tid; i < OC * P * 9; i += 256) {
        int oc   = i / (P * 9);
        int rem2 = i - oc * (P * 9);
        int ic   = rem2 / 9;
        int tap  = rem2 - ic * 9;
        sW[(tap * 16 + ic) * BPITCH + oc] = f2tf32(wgt[i]);
    }
    __syncthreads();   // sTop ready before gather

    // stage patch: 258 pixel slots x 3 rows x 16 ch
    for (int i = tid; i < 258 * 3; i += 256) {
        int pr = i / 258;
        int pp = i - pr * 258;
        int gw = pp - 1;
        int gh = h - 1 + pr;
        uint32_t q[16];
        if (((unsigned)gw < (unsigned)W) && ((unsigned)gh < (unsigned)H)) {
            const float* src = x + ((size_t)b * C) * HW + gh * W + gw;
#pragma unroll
            for (int c = 0; c < 16; c++)
                q[c] = f2tf32(src[(size_t)sTop[c] * HW]);
        } else {
#pragma unroll
            for (int c = 0; c < 16; c++) q[c] = 0u;
        }
        uint32_t* dst = sIn + (pr * AROW + pp) * APITCH;
#pragma unroll
        for (int c = 0; c < 16; c++) dst[c] = q[c];
    }
    __syncthreads();

    // ---- MMA mainloop: warp owns 32 px, all 64 oc ----
    float acc[2][8][4];
#pragma unroll
    for (int m = 0; m < 2; m++)
#pragma unroll
        for (int j = 0; j < 8; j++)
#pragma unroll
            for (int r = 0; r < 4; r++) acc[m][j][r] = 0.f;

    int gp = lane >> 2;
    int kc = lane & 3;
    int pbase = wid * 32 + gp;

#pragma unroll
    for (int tap = 0; tap < 9; tap++) {
        int kh = tap / 3, kw = tap - kh * 3;
        int arow0 = kh * AROW + kw;
#pragma unroll
        for (int ks = 0; ks < 2; ks++) {
            uint32_t a[2][4];
#pragma unroll
            for (int m = 0; m < 2; m++) {
                int p0 = pbase + m * 16;
                a[m][0] = sIn[(arow0 + p0)     * APITCH + ks * 8 + kc];
                a[m][1] = sIn[(arow0 + p0 + 8) * APITCH + ks * 8 + kc];
                a[m][2] = sIn[(arow0 + p0)     * APITCH + ks * 8 + kc + 4];
                a[m][3] = sIn[(arow0 + p0 + 8) * APITCH + ks * 8 + kc + 4];
            }
            int kr = tap * 16 + ks * 8 + kc;
            const uint32_t* brow0 = sW + kr * BPITCH + gp;
            const uint32_t* brow1 = brow0 + 4 * BPITCH;
#pragma unroll
            for (int j = 0; j < 8; j++) {
                uint32_t b0 = brow0[j * 8];
                uint32_t b1 = brow1[j * 8];
#pragma unroll
                for (int m = 0; m < 2; m++) {
                    asm volatile(
                        "mma.sync.aligned.m16n8k8.row.col.f32.tf32.tf32.f32 "
                        "{%0,%1,%2,%3}, {%4,%5,%6,%7}, {%8,%9}, {%0,%1,%2,%3};"
                        : "+f"(acc[m][j][0]), "+f"(acc[m][j][1]),
                          "+f"(acc[m][j][2]), "+f"(acc[m][j][3])
                        : "r"(a[m][0]), "r"(a[m][1]), "r"(a[m][2]), "r"(a[m][3]),
                          "r"(b0), "r"(b1));
                }
            }
        }
    }
    __syncthreads();   // done reading sIn/sW; smem becomes sOut

    // ---- accumulators -> sOut[oc][OPITCH] (conflict-free) ----
#pragma unroll
    for (int m = 0; m < 2; m++) {
        int px = pbase + m * 16;
#pragma unroll
        for (int j = 0; j < 8; j++) {
            int oc0 = j * 8 + 2 * kc;
            sOut[oc0 * OPITCH + px]           = acc[m][j][0];
            sOut[(oc0 + 1) * OPITCH + px]     = acc[m][j][1];
            sOut[oc0 * OPITCH + px + 8]       = acc[m][j][2];
            sOut[(oc0 + 1) * OPITCH + px + 8] = acc[m][j][3];
        }
    }
    __syncthreads();

    // ---- coalesced store: 64 oc rows x 256 px, + bias ----
    int r  = tid >> 2;              // oc row
    int c0 = (tid & 3) * 64;        // 64-px segment
    float bb = sB[r];
    float* ob = out + ((size_t)b * OUTC + r) * HW + h * W + c0;
    const float* sr = sOut + r * OPITCH + c0;
#pragma unroll
    for (int q = 0; q < 16; q++) {
        float4 v = *(const float4*)(sr + q * 4);
        v.x += bb; v.y += bb; v.z += bb; v.w += bb;
        *(float4*)(ob + q * 4) = v;
    }
}

// ===========================================================================
extern "C" void kernel_launch(void* const* d_in, const int* in_sizes, int n_in,
                              void* d_out, int out_size) {
    const float* x    = (const float*)d_in[0];
    const float* wgt  = (const float*)d_in[1];
    const float* bias = (const float*)d_in[2];
    float* out = (float*)d_out;

    cudaFuncSetAttribute(k_conv_mma, cudaFuncAttributeMaxDynamicSharedMemorySize,
                         CONV_SMEM);

    k_stats<<<B * C, 256>>>(x);
    k_topk<<<B, 32>>>();
    k_conv_mma<<<FUSED_GRID, 256, CONV_SMEM>>>(x, wgt, bias, out);
}

// round 6
// speedup vs baseline: 1.9711x; 1.2764x over previous
#include <cuda_runtime.h>
#include <cuda_fp16.h>
#include <math.h>
#include <cstdint>

#define B 8
#define C 64
#define H 256
#define W 256
#define HW 65536
#define P 16
#define OC 64
#define NBINS 256
#define OUTC 112   // OC + (C-P)

// Device scratch
__device__ float g_act[B * C];
__device__ int   g_top[B * P];
__device__ int   g_unsel[B * (C - P)];

// ===========================================================================
// Kernel 1: fused per-(b,c) min/max + 256-bin histogram + entropy.
// 512 threads/block (fills SM with ~55 warps), 16 sub-histograms.
// ===========================================================================
__global__ void __launch_bounds__(512)
k_stats(const float* __restrict__ x) {
    __shared__ float smn[512], smx[512];
    __shared__ int   sh[16][NBINS];
    __shared__ float sred[512];
    __shared__ float s_mn, s_den;

    int bc  = blockIdx.x;
    int tid = threadIdx.x;
    int wid = tid >> 5;
    const float4* p = (const float4*)(x + (size_t)bc * HW);

    float mn = 3.402823466e+38f, mx = -3.402823466e+38f;
    for (int i = tid; i < HW / 4; i += 512) {
        float4 v = p[i];
        mn = fminf(mn, fminf(fminf(v.x, v.y), fminf(v.z, v.w)));
        mx = fmaxf(mx, fmaxf(fmaxf(v.x, v.y), fmaxf(v.z, v.w)));
    }
    smn[tid] = mn; smx[tid] = mx;
    for (int w = 0; w < 16; w++)
        if (tid < NBINS) sh[w][tid] = 0;
    __syncthreads();
    for (int s = 256; s > 0; s >>= 1) {
        if (tid < s) {
            smn[tid] = fminf(smn[tid], smn[tid + s]);
            smx[tid] = fmaxf(smx[tid], smx[tid + s]);
        }
        __syncthreads();
    }
    if (tid == 0) { s_mn = smn[0]; s_den = smx[0] - smn[0] + 1e-8f; }
    __syncthreads();

    float bmn = s_mn, bden = s_den;
    int* myh = sh[wid];
    for (int i = tid; i < HW / 4; i += 512) {
        float4 v = p[i];
        float vs[4] = {v.x, v.y, v.z, v.w};
#pragma unroll
        for (int k = 0; k < 4; k++) {
            float xn = __fdiv_rn(vs[k] - bmn, bden);
            int bn = (int)(xn * 256.0f);
            bn = bn < 0 ? 0 : (bn > 255 ? 255 : bn);
            atomicAdd(&myh[bn], 1);
        }
    }
    __syncthreads();

    float hv = 0.f;
    if (tid < NBINS) {
        int cnt = 0;
#pragma unroll
        for (int w = 0; w < 16; w++) cnt += sh[w][tid];
        hv = (float)cnt + 1e-8f;
    }
    sred[tid] = hv;
    __syncthreads();
    for (int s = 256; s > 0; s >>= 1) {
        if (tid < s) sred[tid] += sred[tid + s];
        __syncthreads();
    }
    float total = sred[0];
    __syncthreads();

    float term = 0.f;
    if (tid < NBINS) {
        float prob = __fdiv_rn(hv, total);
        term = prob * logf(prob + 1e-8f);
    }
    sred[tid] = term;
    __syncthreads();
    for (int s = 256; s > 0; s >>= 1) {
        if (tid < s) sred[tid] += sred[tid + s];
        __syncthreads();
    }
    if (tid == 0) g_act[bc] = -sred[0];
}

// ===========================================================================
// Kernel 2: top-16 per batch (stable tie-break) + ascending unselected list.
// ===========================================================================
__global__ void k_topk() {
    int b = blockIdx.x;
    if (threadIdx.x != 0) return;
    float a[C];
    bool used[C];
    for (int c = 0; c < C; c++) { a[c] = g_act[b * C + c]; used[c] = false; }
    for (int p = 0; p < P; p++) {
        float best = -3.402823466e+38f;
        int bi = -1;
        for (int c = 0; c < C; c++)
            if (!used[c] && a[c] > best) { best = a[c]; bi = c; }
        used[bi] = true;
        g_top[b * P + p] = bi;
    }
    int k = 0;
    for (int c = 0; c < C; c++)
        if (!used[c]) g_unsel[b * (C - P) + (k++)] = c;
}

// ===========================================================================
// Kernel 3 (fused): fp16 mma.m16n8k16 conv (full-row tiles) + untouched-copy.
// bid%3: 0,1 -> conv tile (2048 rows); 2 -> copy chunk (1024 chunks).
//
// Conv tile = 256 px x 64 oc. 8 warps x 32 px (two m16 chunks).
// K = 144 = 9 taps x 16 ch; ONE K=16 k-step per tap -> 144 mma/warp/tile.
// A smem: [3][260 slots] x 12-word pitch, 8 half2 words (16 ch) per slot.
//   bank(gp*12+kc) all-distinct -> conflict-free.
// B smem: [72 rows = tap*8+word][72 pitch] half2 words; bank(kc*8+gp) distinct.
// Epilogue: direct global stores (8-px runs fill 32B sectors).
// ===========================================================================
#define APITCH 12
#define AROW   260
#define SIN_WORDS (3 * AROW * APITCH)        // 9360
#define BPITCH 72
#define SW_WORDS  (72 * BPITCH)              // 5184
#define CONV_SMEM ((SIN_WORDS + SW_WORDS) * 4)   // 58176 bytes
#define NCONV  (B * H)                       // 2048
#define NCOPY  1024
#define FUSED_GRID (NCONV + NCOPY)           // 3072
#define COPY_F4_TOTAL ((size_t)B * (C - P) * (HW / 4))   // 6291456
#define COPY_PER_CHUNK ((int)(COPY_F4_TOTAL / NCOPY))    // 6144

__global__ void __launch_bounds__(256, 2)
k_conv_mma(const float* __restrict__ x, const float* __restrict__ wgt,
           const float* __restrict__ bias, float* __restrict__ out) {
    extern __shared__ uint32_t smem_w[];
    int tid  = threadIdx.x;
    int bid  = blockIdx.x;
    int grp  = bid / 3;
    int role = bid - grp * 3;

    // ---------------- copy role ----------------
    if (role == 2) {
        size_t base = (size_t)grp * COPY_PER_CHUNK;
        for (int i = tid; i < COPY_PER_CHUNK; i += 256) {
            size_t t = base + i;
            int ch_slot = (int)(t >> 14);
            int off     = (int)(t & 16383);
            int b = ch_slot / (C - P);
            int j = ch_slot - b * (C - P);
            int c = g_unsel[b * (C - P) + j];
            const float4* src = (const float4*)(x + ((size_t)(b * C + c)) * HW);
            float4* dst = (float4*)(out + (((size_t)b * OUTC) + OC + j) * HW);
            dst[off] = src[off];
        }
        return;
    }

    // ---------------- conv role ----------------
    uint32_t* sIn = smem_w;               // packed half2, [slot][12-word pitch]
    uint32_t* sW  = smem_w + SIN_WORDS;   // packed half2, [72][BPITCH]
    __shared__ float sB[OC];
    __shared__ int   sTop[P];

    int wid  = tid >> 5;
    int lane = tid & 31;

    int tile = grp * 2 + role;        // 0..2047
    int b = tile >> 8;
    int h = tile & 255;

    if (tid < P)  sTop[tid] = g_top[b * P + tid];
    if (tid < OC) sB[tid]  = bias[tid];

    // stage weights: sW[(tap*8 + w)*BPITCH + oc] = half2(wgt[oc][2w][tap], wgt[oc][2w+1][tap])
    for (int i = tid; i < 72 * OC; i += 256) {
        int oc  = i & 63;
        int row = i >> 6;             // tap*8 + w
        int tap = row >> 3;
        int w2  = row & 7;
        float f0 = wgt[oc * (P * 9) + (2 * w2)     * 9 + tap];
        float f1 = wgt[oc * (P * 9) + (2 * w2 + 1) * 9 + tap];
        __half2 hp = __floats2half2_rn(f0, f1);
        sW[row * BPITCH + oc] = *reinterpret_cast<uint32_t*>(&hp);
    }
    __syncthreads();   // sTop ready before gather

    // stage patch: 258 pixel slots x 3 rows, 16 ch packed as 8 half2 words
    for (int i = tid; i < 258 * 3; i += 256) {
        int pr = i / 258;
        int pp = i - pr * 258;
        int gw = pp - 1;
        int gh = h - 1 + pr;
        uint32_t q[8];
        if (((unsigned)gw < (unsigned)W) && ((unsigned)gh < (unsigned)H)) {
            const float* src = x + ((size_t)b * C) * HW + gh * W + gw;
#pragma unroll
            for (int w2 = 0; w2 < 8; w2++) {
                float f0 = src[(size_t)sTop[2 * w2]     * HW];
                float f1 = src[(size_t)sTop[2 * w2 + 1] * HW];
                __half2 hp = __floats2half2_rn(f0, f1);
                q[w2] = *reinterpret_cast<uint32_t*>(&hp);
            }
        } else {
#pragma unroll
            for (int w2 = 0; w2 < 8; w2++) q[w2] = 0u;
        }
        uint32_t* dst = sIn + (pr * AROW + pp) * APITCH;
        *(uint4*)(dst)     = make_uint4(q[0], q[1], q[2], q[3]);
        *(uint4*)(dst + 4) = make_uint4(q[4], q[5], q[6], q[7]);
    }
    __syncthreads();

    // ---- MMA mainloop: warp owns 32 px, all 64 oc; 1 k-step per tap ----
    float acc[2][8][4];
#pragma unroll
    for (int m = 0; m < 2; m++)
#pragma unroll
        for (int j = 0; j < 8; j++)
#pragma unroll
            for (int r = 0; r < 4; r++) acc[m][j][r] = 0.f;

    int gp = lane >> 2;
    int kc = lane & 3;
    int pbase = wid * 32 + gp;

#pragma unroll
    for (int tap = 0; tap < 9; tap++) {
        int arow0 = (tap / 3) * AROW + (tap % 3);
        uint32_t a[2][4];
#pragma unroll
        for (int m = 0; m < 2; m++) {
            int base0 = (arow0 + pbase + m * 16) * APITCH;
            a[m][0] = sIn[base0 + kc];                   // rows g,   k 2kc..
            a[m][1] = sIn[base0 + 8 * APITCH + kc];      // rows g+8
            a[m][2] = sIn[base0 + kc + 4];               // rows g,   k 2kc+8..
            a[m][3] = sIn[base0 + 8 * APITCH + kc + 4];  // rows g+8
        }
        const uint32_t* b0row = sW + (tap * 8 + kc)     * BPITCH + gp;
        const uint32_t* b1row = sW + (tap * 8 + kc + 4) * BPITCH + gp;
#pragma unroll
        for (int j = 0; j < 8; j++) {
            uint32_t b0 = b0row[j * 8];
            uint32_t b1 = b1row[j * 8];
#pragma unroll
            for (int m = 0; m < 2; m++) {
                asm volatile(
                    "mma.sync.aligned.m16n8k16.row.col.f32.f16.f16.f32 "
                    "{%0,%1,%2,%3}, {%4,%5,%6,%7}, {%8,%9}, {%0,%1,%2,%3};"
                    : "+f"(acc[m][j][0]), "+f"(acc[m][j][1]),
                      "+f"(acc[m][j][2]), "+f"(acc[m][j][3])
                    : "r"(a[m][0]), "r"(a[m][1]), "r"(a[m][2]), "r"(a[m][3]),
                      "r"(b0), "r"(b1));
            }
        }
    }

    // ---- epilogue: direct stores; 8 consecutive px per oc fill 32B sectors ----
    size_t obase = ((size_t)b * OUTC) * HW + (size_t)h * W;
#pragma unroll
    for (int m = 0; m < 2; m++) {
        int px = pbase + m * 16;
#pragma unroll
        for (int j = 0; j < 8; j++) {
            int oc0 = j * 8 + 2 * kc;
            float b0 = sB[oc0], b1 = sB[oc0 + 1];
            float* o0 = out + obase + (size_t)oc0 * HW + px;
            float* o1 = o0 + HW;
            o0[0] = acc[m][j][0] + b0;
            o1[0] = acc[m][j][1] + b1;
            o0[8] = acc[m][j][2] + b0;
            o1[8] = acc[m][j][3] + b1;
        }
    }
}

// ===========================================================================
extern "C" void kernel_launch(void* const* d_in, const int* in_sizes, int n_in,
                              void* d_out, int out_size) {
    const float* x    = (const float*)d_in[0];
    const float* wgt  = (const float*)d_in[1];
    const float* bias = (const float*)d_in[2];
    float* out = (float*)d_out;

    cudaFuncSetAttribute(k_conv_mma, cudaFuncAttributeMaxDynamicSharedMemorySize,
                         CONV_SMEM);

    k_stats<<<B * C, 512>>>(x);
    k_topk<<<B, 32>>>();
    k_conv_mma<<<FUSED_GRID, 256, CONV_SMEM>>>(x, wgt, bias, out);
}

// round 7
// speedup vs baseline: 2.0713x; 1.0508x over previous
#include <cuda_runtime.h>
#include <cuda_fp16.h>
#include <math.h>
#include <cstdint>

#define B 8
#define C 64
#define H 256
#define W 256
#define HW 65536
#define P 16
#define OC 64
#define NBINS 256
#define OUTC 112   // OC + (C-P)

// Device scratch
__device__ float g_act[B * C];
__device__ int   g_top[B * P];
__device__ int   g_unsel[B * (C - P)];

// ===========================================================================
// Kernel 1: fused per-(b,c) min/max + 256-bin histogram + entropy.
// MUFU fix: per-element __fdiv_rn replaced by hoisted reciprocal + Markstein
// correctly-rounded division (1 MUL + 2 FMA, fma-pipe only).
// ===========================================================================
__global__ void __launch_bounds__(512)
k_stats(const float* __restrict__ x) {
    __shared__ float smn[512], smx[512];
    __shared__ int   sh[16][NBINS];
    __shared__ float sred[512];
    __shared__ float s_mn, s_den;

    int bc  = blockIdx.x;
    int tid = threadIdx.x;
    int wid = tid >> 5;
    const float4* p = (const float4*)(x + (size_t)bc * HW);

    float mn = 3.402823466e+38f, mx = -3.402823466e+38f;
    for (int i = tid; i < HW / 4; i += 512) {
        float4 v = p[i];
        mn = fminf(mn, fminf(fminf(v.x, v.y), fminf(v.z, v.w)));
        mx = fmaxf(mx, fmaxf(fmaxf(v.x, v.y), fmaxf(v.z, v.w)));
    }
    smn[tid] = mn; smx[tid] = mx;
    for (int w = 0; w < 16; w++)
        if (tid < NBINS) sh[w][tid] = 0;
    __syncthreads();
    for (int s = 256; s > 0; s >>= 1) {
        if (tid < s) {
            smn[tid] = fminf(smn[tid], smn[tid + s]);
            smx[tid] = fmaxf(smx[tid], smx[tid + s]);
        }
        __syncthreads();
    }
    if (tid == 0) { s_mn = smn[0]; s_den = smx[0] - smn[0] + 1e-8f; }
    __syncthreads();

    float bmn  = s_mn, bden = s_den;
    float binv = __frcp_rn(bden);
    int* myh = sh[wid];
    for (int i = tid; i < HW / 4; i += 512) {
        float4 v = p[i];
        float vs[4] = {v.x, v.y, v.z, v.w};
#pragma unroll
        for (int k = 0; k < 4; k++) {
            float d  = vs[k] - bmn;
            // correctly-rounded division (Markstein): matches __fdiv_rn
            float q0 = d * binv;
            float r  = fmaf(-bden, q0, d);
            float xn = fmaf(r, binv, q0);
            int bn = (int)(xn * 256.0f);
            bn = bn < 0 ? 0 : (bn > 255 ? 255 : bn);
            atomicAdd(&myh[bn], 1);
        }
    }
    __syncthreads();

    float hv = 0.f;
    if (tid < NBINS) {
        int cnt = 0;
#pragma unroll
        for (int w = 0; w < 16; w++) cnt += sh[w][tid];
        hv = (float)cnt + 1e-8f;
    }
    sred[tid] = hv;
    __syncthreads();
    for (int s = 256; s > 0; s >>= 1) {
        if (tid < s) sred[tid] += sred[tid + s];
        __syncthreads();
    }
    float total = sred[0];
    __syncthreads();

    float term = 0.f;
    if (tid < NBINS) {
        float prob = __fdiv_rn(hv, total);   // only 256 of these per block
        term = prob * logf(prob + 1e-8f);
    }
    sred[tid] = term;
    __syncthreads();
    for (int s = 256; s > 0; s >>= 1) {
        if (tid < s) sred[tid] += sred[tid + s];
        __syncthreads();
    }
    if (tid == 0) g_act[bc] = -sred[0];
}

// ===========================================================================
// Kernel 2: top-16 per batch (stable tie-break) + ascending unselected list.
// ===========================================================================
__global__ void k_topk() {
    int b = blockIdx.x;
    if (threadIdx.x != 0) return;
    float a[C];
    bool used[C];
    for (int c = 0; c < C; c++) { a[c] = g_act[b * C + c]; used[c] = false; }
    for (int p = 0; p < P; p++) {
        float best = -3.402823466e+38f;
        int bi = -1;
        for (int c = 0; c < C; c++)
            if (!used[c] && a[c] > best) { best = a[c]; bi = c; }
        used[bi] = true;
        g_top[b * P + p] = bi;
    }
    int k = 0;
    for (int c = 0; c < C; c++)
        if (!used[c]) g_unsel[b * (C - P) + (k++)] = c;
}

// ===========================================================================
// Kernel 3 (fused): fp16 mma.m16n8k16 conv on 2-row tiles + untouched-copy.
// bid%3: 0,1 -> conv tile; 2 -> copy chunk.
//
// Conv tile = 2 rows x 128 px x 64 oc. Staging 4 input rows serves both
// output rows (row sharing: 2.03 staged slots/px vs 3.02 for 1-row tiles).
// 8 warps: wid>>2 = row, wid&3 = 32-px column chunk. K = 144 = 9 taps x
// 16ch, one K=16 k-step per tap.
// A smem: [4 rows][132 slots] x 12-word pitch (8 half2 = 16 ch per slot),
//   bank(gp*12+kc) all-distinct.  B smem: [72][72 pitch], bank(kc*8+gp) ok.
// ===========================================================================
#define APITCH 12
#define AROW   132
#define SIN_WORDS (4 * AROW * APITCH)        // 6336
#define BPITCH 72
#define SW_WORDS  (72 * BPITCH)              // 5184
#define CONV_SMEM ((SIN_WORDS + SW_WORDS) * 4)   // 46080 bytes
#define NCONV  (B * (H / 2) * (W / 128))     // 2048
#define NCOPY  1024
#define FUSED_GRID (NCONV + NCOPY)           // 3072
#define COPY_F4_TOTAL ((size_t)B * (C - P) * (HW / 4))   // 6291456
#define COPY_PER_CHUNK ((int)(COPY_F4_TOTAL / NCOPY))    // 6144

__global__ void __launch_bounds__(256, 2)
k_conv_mma(const float* __restrict__ x, const float* __restrict__ wgt,
           const float* __restrict__ bias, float* __restrict__ out) {
    extern __shared__ uint32_t smem_w[];
    int tid  = threadIdx.x;
    int bid  = blockIdx.x;
    int grp  = bid / 3;
    int role = bid - grp * 3;

    // ---------------- copy role ----------------
    if (role == 2) {
        size_t base = (size_t)grp * COPY_PER_CHUNK;
        for (int i = tid; i < COPY_PER_CHUNK; i += 256) {
            size_t t = base + i;
            int ch_slot = (int)(t >> 14);
            int off     = (int)(t & 16383);
            int b = ch_slot / (C - P);
            int j = ch_slot - b * (C - P);
            int c = g_unsel[b * (C - P) + j];
            const float4* src = (const float4*)(x + ((size_t)(b * C + c)) * HW);
            float4* dst = (float4*)(out + (((size_t)b * OUTC) + OC + j) * HW);
            dst[off] = src[off];
        }
        return;
    }

    // ---------------- conv role ----------------
    uint32_t* sIn = smem_w;               // packed half2
    uint32_t* sW  = smem_w + SIN_WORDS;   // packed half2
    __shared__ float sB[OC];
    __shared__ int   sTop[P];

    int wid  = tid >> 5;
    int lane = tid & 31;

    int t    = grp * 2 + role;            // 0..2047
    int b    = t >> 8;
    int rem  = t & 255;
    int h0   = (rem >> 1) * 2;
    int w0   = (rem & 1) * 128;

    if (tid < P)  sTop[tid] = g_top[b * P + tid];
    if (tid < OC) sB[tid]  = bias[tid];

    // stage weights: sW[(tap*8+w2)*BPITCH + oc] = half2(w[oc][2w2][tap], w[oc][2w2+1][tap])
    for (int i = tid; i < 72 * OC; i += 256) {
        int oc  = i & 63;
        int row = i >> 6;
        int tap = row >> 3;
        int w2  = row & 7;
        float f0 = wgt[oc * (P * 9) + (2 * w2)     * 9 + tap];
        float f1 = wgt[oc * (P * 9) + (2 * w2 + 1) * 9 + tap];
        __half2 hp = __floats2half2_rn(f0, f1);
        sW[row * BPITCH + oc] = *reinterpret_cast<uint32_t*>(&hp);
    }
    __syncthreads();   // sTop visible before gather

    // stage patch: 130 pixel slots x 4 rows, 16 ch packed as 8 half2 words
    for (int i = tid; i < 130 * 4; i += 256) {
        int pr = i / 130;
        int pp = i - pr * 130;
        int gw = w0 - 1 + pp;
        int gh = h0 - 1 + pr;
        uint32_t q[8];
        if (((unsigned)gw < (unsigned)W) && ((unsigned)gh < (unsigned)H)) {
            const float* src = x + ((size_t)b * C) * HW + gh * W + gw;
#pragma unroll
            for (int w2 = 0; w2 < 8; w2++) {
                float f0 = src[(size_t)sTop[2 * w2]     * HW];
                float f1 = src[(size_t)sTop[2 * w2 + 1] * HW];
                __half2 hp = __floats2half2_rn(f0, f1);
                q[w2] = *reinterpret_cast<uint32_t*>(&hp);
            }
        } else {
#pragma unroll
            for (int w2 = 0; w2 < 8; w2++) q[w2] = 0u;
        }
        uint32_t* dst = sIn + (pr * AROW + pp) * APITCH;
        *(uint4*)(dst)     = make_uint4(q[0], q[1], q[2], q[3]);
        *(uint4*)(dst + 4) = make_uint4(q[4], q[5], q[6], q[7]);
    }
    __syncthreads();

    // ---- MMA mainloop: warp owns 32 px of one output row, all 64 oc ----
    float acc[2][8][4];
#pragma unroll
    for (int m = 0; m < 2; m++)
#pragma unroll
        for (int j = 0; j < 8; j++)
#pragma unroll
            for (int r = 0; r < 4; r++) acc[m][j][r] = 0.f;

    int gp = lane >> 2;
    int kc = lane & 3;
    int wrow = wid >> 2;              // output row within tile (0/1)
    int wcol = wid & 3;               // 32-px chunk
    int pbase = wcol * 32 + gp;

#pragma unroll
    for (int tap = 0; tap < 9; tap++) {
        int arow0 = (wrow + tap / 3) * AROW + (tap % 3);
        uint32_t a[2][4];
#pragma unroll
        for (int m = 0; m < 2; m++) {
            int base0 = (arow0 + pbase + m * 16) * APITCH;
            a[m][0] = sIn[base0 + kc];
            a[m][1] = sIn[base0 + 8 * APITCH + kc];
            a[m][2] = sIn[base0 + kc + 4];
            a[m][3] = sIn[base0 + 8 * APITCH + kc + 4];
        }
        const uint32_t* b0row = sW + (tap * 8 + kc)     * BPITCH + gp;
        const uint32_t* b1row = sW + (tap * 8 + kc + 4) * BPITCH + gp;
#pragma unroll
        for (int j = 0; j < 8; j++) {
            uint32_t b0 = b0row[j * 8];
            uint32_t b1 = b1row[j * 8];
#pragma unroll
            for (int m = 0; m < 2; m++) {
                asm volatile(
                    "mma.sync.aligned.m16n8k16.row.col.f32.f16.f16.f32 "
                    "{%0,%1,%2,%3}, {%4,%5,%6,%7}, {%8,%9}, {%0,%1,%2,%3};"
                    : "+f"(acc[m][j][0]), "+f"(acc[m][j][1]),
                      "+f"(acc[m][j][2]), "+f"(acc[m][j][3])
                    : "r"(a[m][0]), "r"(a[m][1]), "r"(a[m][2]), "r"(a[m][3]),
                      "r"(b0), "r"(b1));
            }
        }
    }

    // ---- epilogue: direct stores; 8-px runs fill 32B sectors ----
    size_t obase = ((size_t)b * OUTC) * HW + (size_t)(h0 + wrow) * W + w0;
#pragma unroll
    for (int m = 0; m < 2; m++) {
        int px = pbase + m * 16;
#pragma unroll
        for (int j = 0; j < 8; j++) {
            int oc0 = j * 8 + 2 * kc;
            float b0 = sB[oc0], b1 = sB[oc0 + 1];
            float* o0 = out + obase + (size_t)oc0 * HW + px;
            float* o1 = o0 + HW;
            o0[0] = acc[m][j][0] + b0;
            o1[0] = acc[m][j][1] + b1;
            o0[8] = acc[m][j][2] + b0;
            o1[8] = acc[m][j][3] + b1;
        }
    }
}

// ===========================================================================
extern "C" void kernel_launch(void* const* d_in, const int* in_sizes, int n_in,
                              void* d_out, int out_size) {
    const float* x    = (const float*)d_in[0];
    const float* wgt  = (const float*)d_in[1];
    const float* bias = (const float*)d_in[2];
    float* out = (float*)d_out;

    cudaFuncSetAttribute(k_conv_mma, cudaFuncAttributeMaxDynamicSharedMemorySize,
                         CONV_SMEM);

    k_stats<<<B * C, 512>>>(x);
    k_topk<<<B, 32>>>();
    k_conv_mma<<<FUSED_GRID, 256, CONV_SMEM>>>(x, wgt, bias, out);
}

// round 8
// speedup vs baseline: 2.3108x; 1.1156x over previous
#include <cuda_runtime.h>
#include <cuda_fp16.h>
#include <math.h>
#include <cstdint>

#define B 8
#define C 64
#define H 256
#define W 256
#define HW 65536
#define P 16
#define OC 64
#define NBINS 256
#define OUTC 112   // OC + (C-P)

// Device scratch
__device__ float g_act[B * C];
__device__ int   g_top[B * P];
__device__ int   g_unsel[B * (C - P)];

__device__ __forceinline__ uint32_t smem_u32(const void* p) {
    uint32_t a;
    asm("{ .reg .u64 t; cvta.to.shared.u64 t, %1; cvt.u32.u64 %0, t; }"
        : "=r"(a) : "l"(p));
    return a;
}
__device__ __forceinline__ void cp_async4(uint32_t saddr, const float* g) {
    asm volatile("cp.async.ca.shared.global [%0], [%1], 4;"
                 :: "r"(saddr), "l"(g) : "memory");
}

// ===========================================================================
// Kernel 1: fused per-(b,c) min/max + 256-bin histogram + entropy.
// Hoisted reciprocal + Markstein correctly-rounded division (matches div.rn).
// ===========================================================================
__global__ void __launch_bounds__(512)
k_stats(const float* __restrict__ x) {
    __shared__ float smn[512], smx[512];
    __shared__ int   sh[16][NBINS];
    __shared__ float sred[512];
    __shared__ float s_mn, s_den;

    int bc  = blockIdx.x;
    int tid = threadIdx.x;
    int wid = tid >> 5;
    const float4* p = (const float4*)(x + (size_t)bc * HW);

    float mn = 3.402823466e+38f, mx = -3.402823466e+38f;
#pragma unroll 4
    for (int i = tid; i < HW / 4; i += 512) {
        float4 v = p[i];
        mn = fminf(mn, fminf(fminf(v.x, v.y), fminf(v.z, v.w)));
        mx = fmaxf(mx, fmaxf(fmaxf(v.x, v.y), fmaxf(v.z, v.w)));
    }
    smn[tid] = mn; smx[tid] = mx;
    for (int w = 0; w < 16; w++)
        if (tid < NBINS) sh[w][tid] = 0;
    __syncthreads();
    for (int s = 256; s > 0; s >>= 1) {
        if (tid < s) {
            smn[tid] = fminf(smn[tid], smn[tid + s]);
            smx[tid] = fmaxf(smx[tid], smx[tid + s]);
        }
        __syncthreads();
    }
    if (tid == 0) { s_mn = smn[0]; s_den = smx[0] - smn[0] + 1e-8f; }
    __syncthreads();

    float bmn  = s_mn, bden = s_den;
    float binv = __frcp_rn(bden);
    int* myh = sh[wid];
#pragma unroll 2
    for (int i = tid; i < HW / 4; i += 512) {
        float4 v = p[i];
        float vs[4] = {v.x, v.y, v.z, v.w};
#pragma unroll
        for (int k = 0; k < 4; k++) {
            float d  = vs[k] - bmn;
            float q0 = d * binv;
            float r  = fmaf(-bden, q0, d);
            float xn = fmaf(r, binv, q0);
            int bn = (int)(xn * 256.0f);
            bn = bn < 0 ? 0 : (bn > 255 ? 255 : bn);
            atomicAdd(&myh[bn], 1);
        }
    }
    __syncthreads();

    float hv = 0.f;
    if (tid < NBINS) {
        int cnt = 0;
#pragma unroll
        for (int w = 0; w < 16; w++) cnt += sh[w][tid];
        hv = (float)cnt + 1e-8f;
    }
    sred[tid] = hv;
    __syncthreads();
    for (int s = 256; s > 0; s >>= 1) {
        if (tid < s) sred[tid] += sred[tid + s];
        __syncthreads();
    }
    float total = sred[0];
    __syncthreads();

    float term = 0.f;
    if (tid < NBINS) {
        float prob = __fdiv_rn(hv, total);
        term = prob * logf(prob + 1e-8f);
    }
    sred[tid] = term;
    __syncthreads();
    for (int s = 256; s > 0; s >>= 1) {
        if (tid < s) sred[tid] += sred[tid + s];
        __syncthreads();
    }
    if (tid == 0) g_act[bc] = -sred[0];
}

// ===========================================================================
// Kernel 2: top-16 per batch + ascending unselected list (smem-assisted).
// ===========================================================================
__global__ void k_topk() {
    __shared__ float sa[C];
    int b = blockIdx.x;
    if (threadIdx.x < C) sa[threadIdx.x] = g_act[b * C + threadIdx.x];
    __syncthreads();
    if (threadIdx.x != 0) return;
    bool used[C];
    for (int c = 0; c < C; c++) used[c] = false;
    for (int p = 0; p < P; p++) {
        float best = -3.402823466e+38f;
        int bi = -1;
        for (int c = 0; c < C; c++)
            if (!used[c] && sa[c] > best) { best = sa[c]; bi = c; }
        used[bi] = true;
        g_top[b * P + p] = bi;
    }
    int k = 0;
    for (int c = 0; c < C; c++)
        if (!used[c]) g_unsel[b * (C - P) + (k++)] = c;
}

// ===========================================================================
// Kernel 3: persistent pipelined fp16 mma conv + fused untouched-copy.
// 296 CTAs (2/SM), each walks tiles with stride 296. Per tile:
//   wait cp.async(t) -> convert raw->packed half2 -> issue cp.async(t+1)
//   -> mma mainloop(t) -> direct stores -> copy chunk(t).
// Tile = 2 rows x 128 px x 64 oc; K = 144 (9 taps x 16 ch), one K=16
// k-step per tap. Raw fp32 staging pitch 20 words (conflict-free LDS.128);
// packed pitch 12 (conflict-free frag loads); B pitch 72.
// ===========================================================================
#define APITCH 12
#define RPITCH 20
#define AROW   132
#define NSLOT  520                           // 130 x 4 active slots
#define RAW_WORDS (4 * AROW * RPITCH)        // 10560
#define PKD_WORDS (4 * AROW * APITCH)        // 6336
#define BPITCH 72
#define SW_WORDS  (72 * BPITCH)              // 5184
#define CONV_SMEM ((RAW_WORDS + PKD_WORDS + SW_WORDS) * 4)  // 88320 bytes
#define NTILES (B * (H / 2) * (W / 128))     // 2048
#define NCTA   296
#define COPY_F4_PER_TILE 3072                // 6291456 / 2048

__global__ void __launch_bounds__(256, 2)
k_conv_mma(const float* __restrict__ x, const float* __restrict__ wgt,
           const float* __restrict__ bias, float* __restrict__ out) {
    extern __shared__ uint32_t smem_w[];
    uint32_t* rawW = smem_w;                       // fp32 gather staging
    uint32_t* sIn  = smem_w + RAW_WORDS;           // packed half2
    uint32_t* sW   = smem_w + RAW_WORDS + PKD_WORDS;
    __shared__ float sB[OC];

    int tid  = threadIdx.x;
    int wid  = tid >> 5;
    int lane = tid & 31;
    uint32_t rawA = smem_u32(rawW);

    // ---- one-time staging: weights (half2, [72][BPITCH]) + bias ----
    for (int i = tid; i < 72 * OC; i += 256) {
        int oc  = i & 63;
        int row = i >> 6;
        int tap = row >> 3;
        int w2  = row & 7;
        float f0 = wgt[oc * (P * 9) + (2 * w2)     * 9 + tap];
        float f1 = wgt[oc * (P * 9) + (2 * w2 + 1) * 9 + tap];
        __half2 hp = __floats2half2_rn(f0, f1);
        sW[row * BPITCH + oc] = *reinterpret_cast<uint32_t*>(&hp);
    }
    if (tid < OC) sB[tid] = bias[tid];

    int gp = lane >> 2;
    int kc = lane & 3;
    int wrow = wid >> 2;
    int wcol = wid & 3;
    int pbase = wcol * 32 + gp;

    // ---- stage-issue helper (cp.async fp32 gather for a tile) ----
    auto stage_issue = [&](int tile) {
        int tb  = tile >> 8;
        int rem = tile & 255;
        int h0  = (rem >> 1) * 2;
        int w0  = (rem & 1) * 128;
        int ch[16];
#pragma unroll
        for (int c = 0; c < 16; c++) ch[c] = __ldg(&g_top[tb * P + c]);
        const float* xb = x + ((size_t)tb * C) * HW;
        for (int i = tid; i < NSLOT; i += 256) {
            int pr = i / 130;
            int pp = i - pr * 130;
            int gw = w0 - 1 + pp;
            int gh = h0 - 1 + pr;
            uint32_t dst = rawA + (uint32_t)((pr * AROW + pp) * RPITCH) * 4u;
            if (((unsigned)gw < (unsigned)W) && ((unsigned)gh < (unsigned)H)) {
                const float* src = xb + gh * W + gw;
#pragma unroll
                for (int c = 0; c < 16; c++)
                    cp_async4(dst + c * 4u, src + (size_t)ch[c] * HW);
            } else {
                uint4 z = make_uint4(0u, 0u, 0u, 0u);
#pragma unroll
                for (int q = 0; q < 4; q++)
                    *(uint4*)((char*)rawW + (dst - rawA) + q * 16) = z;
            }
        }
        asm volatile("cp.async.commit_group;" ::: "memory");
    };

    // first tile for this CTA
    int t0 = blockIdx.x;
    if (t0 < NTILES) stage_issue(t0);
    __syncthreads();   // weights/bias visible (and harmless ordering)

    for (int t = t0; t < NTILES; t += NCTA) {
        // ---- wait staged data for tile t ----
        asm volatile("cp.async.wait_group 0;" ::: "memory");
        __syncthreads();

        // ---- convert raw fp32 -> packed half2 ----
        for (int i = tid; i < NSLOT; i += 256) {
            int pr = i / 130;
            int pp = i - pr * 130;
            const float4* rs = (const float4*)(rawW + (pr * AROW + pp) * RPITCH);
            float4 r0 = rs[0], r1 = rs[1], r2 = rs[2], r3 = rs[3];
            __half2 h0 = __floats2half2_rn(r0.x, r0.y);
            __half2 h1 = __floats2half2_rn(r0.z, r0.w);
            __half2 h2 = __floats2half2_rn(r1.x, r1.y);
            __half2 h3 = __floats2half2_rn(r1.z, r1.w);
            __half2 h4 = __floats2half2_rn(r2.x, r2.y);
            __half2 h5 = __floats2half2_rn(r2.z, r2.w);
            __half2 h6 = __floats2half2_rn(r3.x, r3.y);
            __half2 h7 = __floats2half2_rn(r3.z, r3.w);
            uint32_t* dst = sIn + (pr * AROW + pp) * APITCH;
            *(uint4*)(dst) = make_uint4(
                *reinterpret_cast<uint32_t*>(&h0), *reinterpret_cast<uint32_t*>(&h1),
                *reinterpret_cast<uint32_t*>(&h2), *reinterpret_cast<uint32_t*>(&h3));
            *(uint4*)(dst + 4) = make_uint4(
                *reinterpret_cast<uint32_t*>(&h4), *reinterpret_cast<uint32_t*>(&h5),
                *reinterpret_cast<uint32_t*>(&h6), *reinterpret_cast<uint32_t*>(&h7));
        }
        __syncthreads();   // packed ready; raw free for next stage

        // ---- prefetch next tile ----
        int tn = t + NCTA;
        if (tn < NTILES) stage_issue(tn);

        // ---- mainloop ----
        int b   = t >> 8;
        int rem = t & 255;
        int h0  = (rem >> 1) * 2;
        int w0  = (rem & 1) * 128;

        float acc[2][8][4];
#pragma unroll
        for (int m = 0; m < 2; m++)
#pragma unroll
            for (int j = 0; j < 8; j++)
#pragma unroll
                for (int r = 0; r < 4; r++) acc[m][j][r] = 0.f;

#pragma unroll
        for (int tap = 0; tap < 9; tap++) {
            int arow0 = (wrow + tap / 3) * AROW + (tap % 3);
            uint32_t a[2][4];
#pragma unroll
            for (int m = 0; m < 2; m++) {
                int base0 = (arow0 + pbase + m * 16) * APITCH;
                a[m][0] = sIn[base0 + kc];
                a[m][1] = sIn[base0 + 8 * APITCH + kc];
                a[m][2] = sIn[base0 + kc + 4];
                a[m][3] = sIn[base0 + 8 * APITCH + kc + 4];
            }
            const uint32_t* b0row = sW + (tap * 8 + kc)     * BPITCH + gp;
            const uint32_t* b1row = sW + (tap * 8 + kc + 4) * BPITCH + gp;
#pragma unroll
            for (int j = 0; j < 8; j++) {
                uint32_t b0 = b0row[j * 8];
                uint32_t b1 = b1row[j * 8];
#pragma unroll
                for (int m = 0; m < 2; m++) {
                    asm volatile(
                        "mma.sync.aligned.m16n8k16.row.col.f32.f16.f16.f32 "
                        "{%0,%1,%2,%3}, {%4,%5,%6,%7}, {%8,%9}, {%0,%1,%2,%3};"
                        : "+f"(acc[m][j][0]), "+f"(acc[m][j][1]),
                          "+f"(acc[m][j][2]), "+f"(acc[m][j][3])
                        : "r"(a[m][0]), "r"(a[m][1]), "r"(a[m][2]), "r"(a[m][3]),
                          "r"(b0), "r"(b1));
                }
            }
        }

        // ---- direct stores (8-px runs fill 32B sectors) ----
        size_t obase = ((size_t)b * OUTC) * HW + (size_t)(h0 + wrow) * W + w0;
#pragma unroll
        for (int m = 0; m < 2; m++) {
            int px = pbase + m * 16;
#pragma unroll
            for (int j = 0; j < 8; j++) {
                int oc0 = j * 8 + 2 * kc;
                float bb0 = sB[oc0], bb1 = sB[oc0 + 1];
                float* o0 = out + obase + (size_t)oc0 * HW + px;
                float* o1 = o0 + HW;
                o0[0] = acc[m][j][0] + bb0;
                o1[0] = acc[m][j][1] + bb1;
                o0[8] = acc[m][j][2] + bb0;
                o1[8] = acc[m][j][3] + bb1;
            }
        }

        // ---- fused copy chunk for this tile index ----
        {
            size_t base = (size_t)t * COPY_F4_PER_TILE;
#pragma unroll 4
            for (int i = tid; i < COPY_F4_PER_TILE; i += 256) {
                size_t tt = base + i;
                int ch_slot = (int)(tt >> 14);
                int off     = (int)(tt & 16383);
                int cb = ch_slot / (C - P);
                int j  = ch_slot - cb * (C - P);
                int cc = g_unsel[cb * (C - P) + j];
                const float4* src = (const float4*)(x + ((size_t)(cb * C + cc)) * HW);
                float4* dst = (float4*)(out + (((size_t)cb * OUTC) + OC + j) * HW);
                dst[off] = src[off];
            }
        }
        __syncthreads();   // all mainloop/copy done before next convert
    }
}

// ===========================================================================
extern "C" void kernel_launch(void* const* d_in, const int* in_sizes, int n_in,
                              void* d_out, int out_size) {
    const float* x    = (const float*)d_in[0];
    const float* wgt  = (const float*)d_in[1];
    const float* bias = (const float*)d_in[2];
    float* out = (float*)d_out;

    cudaFuncSetAttribute(k_conv_mma, cudaFuncAttributeMaxDynamicSharedMemorySize,
                         CONV_SMEM);

    k_stats<<<B * C, 512>>>(x);
    k_topk<<<B, 64>>>();
    k_conv_mma<<<NCTA, 256, CONV_SMEM>>>(x, wgt, bias, out);
}